// round 1
// baseline (speedup 1.0000x reference)
#include <cuda_runtime.h>
#include <math.h>

#define MAXN    8192
#define THREADS 256
#define JT      512

// Scratch (device globals — no allocation allowed in kernel_launch).
// g_?a: (2*a0, 2*a1, 2*a2, -|a|^2)  "row side"
// g_?b: (  b0,   b1,   b2, -|b|^2)  "column side"
// where a = point * sqrt(log2e / ks), so EX2(arg) = exp(-d2/ks).
__device__ float4 g_xa[MAXN];
__device__ float4 g_xb[MAXN];
__device__ float4 g_za[MAXN];
__device__ float4 g_zb[MAXN];
__device__ double g_acc[3];   // 0: Sxx (strict upper), 1: Szz (strict upper), 2: Sxz (full)

__device__ __forceinline__ float ex2f(float v) {
    float y;
    asm("ex2.approx.ftz.f32 %0, %1;" : "=f"(y) : "f"(v));
    return y;
}

__global__ void prep_kernel(const float* __restrict__ x,
                            const float* __restrict__ z,
                            const float* __restrict__ ks, int n) {
    int i = blockIdx.x * blockDim.x + threadIdx.x;
    if (i == 0) { g_acc[0] = 0.0; g_acc[1] = 0.0; g_acc[2] = 0.0; }
    if (i >= n) return;
    // c = log2(e)/ks ;  a = x*sqrt(c)  =>  2^{-(|a-b|^2)} = exp(-|x-z|^2/ks)
    float sc = sqrtf(1.4426950408889634f / ks[0]);
    float a0 = x[3 * i + 0] * sc;
    float a1 = x[3 * i + 1] * sc;
    float a2 = x[3 * i + 2] * sc;
    float na = a0 * a0 + a1 * a1 + a2 * a2;
    g_xa[i] = make_float4(2.f * a0, 2.f * a1, 2.f * a2, -na);
    g_xb[i] = make_float4(a0, a1, a2, -na);
    float b0 = z[3 * i + 0] * sc;
    float b1 = z[3 * i + 1] * sc;
    float b2 = z[3 * i + 2] * sc;
    float nb = b0 * b0 + b1 * b1 + b2 * b2;
    g_za[i] = make_float4(2.f * b0, 2.f * b1, 2.f * b2, -nb);
    g_zb[i] = make_float4(b0, b1, b2, -nb);
}

// One launch covers all three jobs. Task space per job: (n/THREADS) i-tiles
// x (n/JT) j-slabs. Symmetric jobs (xx, zz) compute the strict upper triangle
// only; blocks entirely below the diagonal exit immediately, blocks entirely
// above run a predicate-free inner loop, boundary blocks use the predicated loop.
__global__ void __launch_bounds__(THREADS) pair_kernel(int n) {
    const int iTiles = n / THREADS;
    const int jSlabs = n / JT;
    const int tpj = iTiles * jSlabs;

    int task = blockIdx.x;
    int job = task / tpj;
    int rem = task - job * tpj;
    int it = rem % iTiles;
    int js = rem / iTiles;

    const float4* A;
    const float4* B;
    bool sym;
    int accIdx;
    if (job == 0)      { A = g_xa; B = g_zb; sym = false; accIdx = 2; }
    else if (job == 1) { A = g_xa; B = g_xb; sym = true;  accIdx = 0; }
    else               { A = g_za; B = g_zb; sym = true;  accIdx = 1; }

    const int i0 = it * THREADS;
    const int j0 = js * JT;

    // Entire slab at or below the smallest row of this tile -> no strict-upper work.
    if (sym && (j0 + JT <= i0 + 1)) return;

    __shared__ float4 sB[JT];
    for (int k = threadIdx.x; k < JT; k += THREADS) sB[k] = B[j0 + k];
    __syncthreads();

    const int i = i0 + threadIdx.x;
    const float4 a = A[i];
    float acc = 0.f;

    const bool boundary = sym && (j0 < i0 + THREADS);
    if (!boundary) {
        // Full tile: every (i, j) pair valid.
#pragma unroll 8
        for (int k = 0; k < JT; k++) {
            float4 b = sB[k];
            float s = a.w + b.w;
            s = fmaf(a.x, b.x, s);
            s = fmaf(a.y, b.y, s);
            s = fmaf(a.z, b.z, s);
            acc += ex2f(s);
        }
    } else {
        // Diagonal-crossing tile: need j (= j0+k) > i, i.e. k > i - j0.
        const int jrel = i - j0;
#pragma unroll 8
        for (int k = 0; k < JT; k++) {
            float4 b = sB[k];
            float s = a.w + b.w;
            s = fmaf(a.x, b.x, s);
            s = fmaf(a.y, b.y, s);
            s = fmaf(a.z, b.z, s);
            float e = ex2f(s);
            if (k > jrel) acc += e;
        }
    }

    // Block reduce (fp32) then one fp64 atomic per block.
#pragma unroll
    for (int o = 16; o > 0; o >>= 1) acc += __shfl_xor_sync(0xffffffffu, acc, o);
    __shared__ float ws[THREADS / 32];
    int lane = threadIdx.x & 31;
    int wid = threadIdx.x >> 5;
    if (lane == 0) ws[wid] = acc;
    __syncthreads();
    if (threadIdx.x == 0) {
        float s = 0.f;
#pragma unroll
        for (int w = 0; w < THREADS / 32; w++) s += ws[w];
        atomicAdd(&g_acc[accIdx], (double)s);
    }
}

__global__ void final_kernel(const float* __restrict__ ks,
                             const float* __restrict__ theta,
                             float* __restrict__ out_scalar, int n) {
    double inv = 1.0 / sqrt(2.0 * 3.14159265358979323846 * (double)ks[0]);
    double nn = (double)n * (double)n;
    // Symmetric sums: full = 2*upper + N diagonal terms of exp(0)=1.
    double mxx = (2.0 * g_acc[0] + (double)n) * inv / nn;
    double mzz = (2.0 * g_acc[1] + (double)n) * inv / nn;
    double mxz = g_acc[2] * inv / nn;
    double r = log(sqrt(mxx * mzz + 1e-5) / (mxz + 1e-5));
    *out_scalar = (float)(r * (double)theta[0]);
}

extern "C" void kernel_launch(void* const* d_in, const int* in_sizes, int n_in,
                              void* d_out, int out_size) {
    const float* x     = (const float*)d_in[0];
    const float* z     = (const float*)d_in[1];
    const float* ks    = (const float*)d_in[2];
    const float* theta = (const float*)d_in[3];
    float* out = (float*)d_out;

    const int nx = in_sizes[0];       // 8192*3
    const int nz = in_sizes[1];
    const int n  = nx / 3;

    // Passthrough outputs: (x, z, scalar)
    cudaMemcpyAsync(out, x, (size_t)nx * sizeof(float),
                    cudaMemcpyDeviceToDevice, 0);
    cudaMemcpyAsync(out + nx, z, (size_t)nz * sizeof(float),
                    cudaMemcpyDeviceToDevice, 0);

    prep_kernel<<<(n + 255) / 256, 256>>>(x, z, ks, n);

    const int iTiles = n / THREADS;
    const int jSlabs = n / JT;
    pair_kernel<<<3 * iTiles * jSlabs, THREADS>>>(n);

    final_kernel<<<1, 1>>>(ks, theta, out + nx + nz, n);
}

// round 3
// speedup vs baseline: 1.0567x; 1.0567x over previous
#include <cuda_runtime.h>
#include <math.h>

#define THREADS 256
#define JT      256
#define MAXBLK  8192

typedef unsigned long long ull;

// Per-block partial sums: [0,tpj) = Sxz, [tpj,2tpj) = Sxx(upper), [2tpj,3tpj) = Szz(upper)
__device__ float g_part[MAXBLK];

__device__ __forceinline__ float ex2f(float v) {
    float y;
    asm("ex2.approx.ftz.f32 %0, %1;" : "=f"(y) : "f"(v));
    return y;
}

// One fused kernel: inline prep (scale + pack), passthrough copy, pair sums.
// Job 0: xz (full grid), job 1: xx (strict upper), job 2: zz (strict upper).
// With JT == THREADS, symmetric blocks: js < it -> empty, js == it -> boundary,
// js > it -> full (predicate-free packed loop).
__global__ void __launch_bounds__(THREADS) pair_kernel(
    const float* __restrict__ x, const float* __restrict__ z,
    const float* __restrict__ ks, float* __restrict__ out, int n)
{
    const int iTiles = n / THREADS;
    const int jSlabs = n / JT;
    const int tpj = iTiles * jSlabs;

    const int b = blockIdx.x;
    const int job = b / tpj;
    const int rem = b - job * tpj;
    const int it = rem % iTiles;
    const int js = rem / iTiles;

    // ---- Passthrough copy: out[0..3n) = x, out[3n..6n) = z, sliced by block ----
    {
        const int total = 6 * n;
        const int per = (total + gridDim.x - 1) / gridDim.x;
        const int start = b * per;
        const int stop = min(start + per, total);
        for (int idx = start + threadIdx.x; idx < stop; idx += THREADS)
            out[idx] = (idx < 3 * n) ? x[idx] : z[idx - 3 * n];
    }

    const bool sym = (job >= 1);
    const int i0 = it * THREADS;
    const int j0 = js * JT;

    if (sym && js < it) {               // entirely below diagonal: no pairs
        if (threadIdx.x == 0) g_part[b] = 0.f;
        return;
    }

    const float* A = (job == 2) ? z : x;
    const float* B = (job == 1) ? x : z;

    const float sc = sqrtf(1.4426950408889634f / ks[0]);   // sqrt(log2e / ks)

    // B slab, packed-pairs layout for f32x2 math:
    //   sB[2*g]   = (bx0, bx1, by0, by1)
    //   sB[2*g+1] = (bz0, bz1, w0,  w1)    w = -|b|^2 (scaled)
    __shared__ float4 sB[JT];
    for (int g = threadIdx.x; g < JT / 2; g += THREADS) {
        int ja = j0 + 2 * g, jb = ja + 1;
        float b0x = B[3 * ja]     * sc, b0y = B[3 * ja + 1] * sc, b0z = B[3 * ja + 2] * sc;
        float b1x = B[3 * jb]     * sc, b1y = B[3 * jb + 1] * sc, b1z = B[3 * jb + 2] * sc;
        float w0 = -(b0x * b0x + b0y * b0y + b0z * b0z);
        float w1 = -(b1x * b1x + b1y * b1y + b1z * b1z);
        sB[2 * g]     = make_float4(b0x, b1x, b0y, b1y);
        sB[2 * g + 1] = make_float4(b0z, b1z, w0, w1);
    }

    // A point for this thread: doubled scaled coords; aw = -|a|^2.
    const int i = i0 + threadIdx.x;
    const float ax = A[3 * i]     * sc * 2.f;
    const float ay = A[3 * i + 1] * sc * 2.f;
    const float az = A[3 * i + 2] * sc * 2.f;
    const float aw = -0.25f * (ax * ax + ay * ay + az * az);
    __syncthreads();

    float acc0 = 0.f, acc1 = 0.f;

    if (!(sym && js == it)) {
        // Full tile: predicate-free packed loop, 2 j's per iteration.
        ull ax2, ay2, az2;
        asm("mov.b64 %0, {%1,%1};" : "=l"(ax2) : "f"(ax));
        asm("mov.b64 %0, {%1,%1};" : "=l"(ay2) : "f"(ay));
        asm("mov.b64 %0, {%1,%1};" : "=l"(az2) : "f"(az));
        unsigned sb = (unsigned)__cvta_generic_to_shared(sB);
#pragma unroll 8
        for (int k2 = 0; k2 < JT / 2; k2++) {
            ull p0, p1, q0, q1, s;
            asm("ld.shared.v2.u64 {%0,%1},[%2];" : "=l"(p0), "=l"(p1) : "r"(sb + k2 * 32));
            asm("ld.shared.v2.u64 {%0,%1},[%2];" : "=l"(q0), "=l"(q1) : "r"(sb + k2 * 32 + 16));
            asm("fma.rn.f32x2 %0,%1,%2,%3;" : "=l"(s) : "l"(ax2), "l"(p0), "l"(q1));
            asm("fma.rn.f32x2 %0,%1,%2,%0;" : "+l"(s) : "l"(ay2), "l"(p1));
            asm("fma.rn.f32x2 %0,%1,%2,%0;" : "+l"(s) : "l"(az2), "l"(q0));
            float s0, s1;
            asm("mov.b64 {%0,%1}, %2;" : "=f"(s0), "=f"(s1) : "l"(s));
            acc0 += ex2f(s0);
            acc1 += ex2f(s1);
        }
    } else {
        // Diagonal tile (j0 == i0): scalar predicated loop; keep j > i, i.e. k > tid.
        const int tid = threadIdx.x;
        const float* f = (const float*)sB;
#pragma unroll 4
        for (int k = 0; k < JT; k++) {
            int k2 = k >> 1, l = k & 1;
            float bx = f[8 * k2 + l];
            float by = f[8 * k2 + 2 + l];
            float bz = f[8 * k2 + 4 + l];
            float bw = f[8 * k2 + 6 + l];
            float s = fmaf(ax, bx, bw);
            s = fmaf(ay, by, s);
            s = fmaf(az, bz, s);
            float e = ex2f(s);
            if (k > tid) acc0 += e;
        }
    }

    // Per-thread factor 2^{aw}, then block reduce -> one partial per block.
    float acc = (acc0 + acc1) * ex2f(aw);
#pragma unroll
    for (int o = 16; o > 0; o >>= 1) acc += __shfl_xor_sync(0xffffffffu, acc, o);
    __shared__ float ws[THREADS / 32];
    const int lane = threadIdx.x & 31;
    const int wid = threadIdx.x >> 5;
    if (lane == 0) ws[wid] = acc;
    __syncthreads();
    if (threadIdx.x == 0) {
        float s = 0.f;
#pragma unroll
        for (int w = 0; w < THREADS / 32; w++) s += ws[w];
        g_part[b] = s;
    }
}

__global__ void final_kernel(const float* __restrict__ ks,
                             const float* __restrict__ theta,
                             float* __restrict__ out_scalar, int n, int tpj) {
    const int t = threadIdx.x;
    double s0 = 0.0, s1 = 0.0, s2 = 0.0;   // xz, xx, zz
    for (int bk = t; bk < tpj; bk += blockDim.x) {
        s0 += (double)g_part[bk];
        s1 += (double)g_part[tpj + bk];
        s2 += (double)g_part[2 * tpj + bk];
    }
#pragma unroll
    for (int o = 16; o > 0; o >>= 1) {
        s0 += __shfl_xor_sync(0xffffffffu, s0, o);
        s1 += __shfl_xor_sync(0xffffffffu, s1, o);
        s2 += __shfl_xor_sync(0xffffffffu, s2, o);
    }
    __shared__ double r0[32], r1[32], r2[32];
    const int lane = t & 31, wid = t >> 5;
    if (lane == 0) { r0[wid] = s0; r1[wid] = s1; r2[wid] = s2; }
    __syncthreads();
    if (t == 0) {
        const int nw = blockDim.x >> 5;
        double t0 = 0, t1 = 0, t2 = 0;
        for (int w = 0; w < nw; w++) { t0 += r0[w]; t1 += r1[w]; t2 += r2[w]; }
        double inv = 1.0 / sqrt(2.0 * 3.14159265358979323846 * (double)ks[0]);
        double nn = (double)n * (double)n;
        double mxz = t0 * inv / nn;
        double mxx = (2.0 * t1 + (double)n) * inv / nn;   // upper*2 + diagonal (exp(0)=1)
        double mzz = (2.0 * t2 + (double)n) * inv / nn;
        double r = log(sqrt(mxx * mzz + 1e-5) / (mxz + 1e-5));
        *out_scalar = (float)(r * (double)theta[0]);
    }
}

extern "C" void kernel_launch(void* const* d_in, const int* in_sizes, int n_in,
                              void* d_out, int out_size) {
    const float* x     = (const float*)d_in[0];
    const float* z     = (const float*)d_in[1];
    const float* ks    = (const float*)d_in[2];
    const float* theta = (const float*)d_in[3];
    float* out = (float*)d_out;

    const int n = in_sizes[0] / 3;          // 8192
    const int iTiles = n / THREADS;
    const int jSlabs = n / JT;
    const int tpj = iTiles * jSlabs;

    pair_kernel<<<3 * tpj, THREADS>>>(x, z, ks, out, n);
    final_kernel<<<1, 1024>>>(ks, theta, out + 6 * n, n, tpj);
}